// round 15
// baseline (speedup 1.0000x reference)
#include <cuda_runtime.h>
#include <cuda_fp16.h>
#include <cstdint>

// HexConv, persistent-CTA fp16 mma.sync (m16n8k16, f32 accum):
//   R10 warp layout (16 warps = 4 M-groups x 4 N-quarters, frags f = wm+4u, u<3,
//   24 acc/thread) + R14 double-buffered fp16 grid (convert(b+1) during compute(b),
//   ONE barrier per batch, no prefetch registers) + deepened MLP (12 LDS.128 in
//   flight per chunk: 4 W + 8 A for u=0,1; then u=2's 4).
// K-permutation: per 32-k superblock, thread lc owns orig d = 8lc..8lc+7 -> all
// operand traffic is LDS.128; CELLB/WROWB == 64 mod 128 -> conflict-free phases.

#define NHEX   165
#define HD     64
#define OUTD   64
#define NCHUNK 7
#define CELLB  192
#define WROWB  960
#define NB     2048
#define THREADS 512
#define GRIDX  152

#define G_BYTES (221 * CELLB)                 // 42432 per buffer
#define W_BYTES (OUTD * WROWB)                // 61440
#define SMEM_BYTES (2 * G_BYTES + W_BYTES)    // 146304

__constant__ int OFFC[7] = {-17 * CELLB, -16 * CELLB, -1 * CELLB, 0,
                            1 * CELLB, 17 * CELLB, 18 * CELLB};

static __device__ __forceinline__ uint32_t pk(float a, float b) {
    __half2 h = __floats2half2_rn(a, b);
    return *(uint32_t*)&h;
}
static __device__ __forceinline__ void mma16816(float* c,
                                                uint32_t a0, uint32_t a1, uint32_t a2, uint32_t a3,
                                                uint32_t b0, uint32_t b1) {
    asm volatile(
        "mma.sync.aligned.m16n8k16.row.col.f32.f16.f16.f32 "
        "{%0,%1,%2,%3}, {%4,%5,%6,%7}, {%8,%9}, {%0,%1,%2,%3};"
        : "+f"(c[0]), "+f"(c[1]), "+f"(c[2]), "+f"(c[3])
        : "r"(a0), "r"(a1), "r"(a2), "r"(a3), "r"(b0), "r"(b1));
}

__global__ void __launch_bounds__(THREADS, 1)
hexconv_mma(const float* __restrict__ x, const float* __restrict__ W,
            const float* __restrict__ bias, float* __restrict__ out)
{
    extern __shared__ char smem[];
    char* G0 = smem;
    char* G1 = smem + G_BYTES;
    char* Wc = smem + 2 * G_BYTES;
    const int tid = threadIdx.x;

    // ---- one-time: zero both grid buffers (pad cells stay zero forever) ----
    for (int i = tid; i < 2 * G_BYTES / 16; i += THREADS)
        ((uint4*)smem)[i] = make_uint4(0, 0, 0, 0);

    // ---- one-time: stage W as fp16 ----
    const float4* Wg4 = (const float4*)W;
    for (int i = tid; i < OUTD * 112; i += THREADS) {
        int o = i / 112, k4 = i - o * 112;
        float4 v = Wg4[i];
        *(uint2*)(Wc + o * WROWB + k4 * 8) = make_uint2(pk(v.x, v.y), pk(v.z, v.w));
    }

    // ---- warp geometry: 16 warps = 4 M-groups x 4 N-quarters (R10 layout) ----
    const int wid = tid >> 5, lane = tid & 31;
    const int wm = wid & 3;        // M group: frags f = wm + 4u, u < 3
    const int wn = wid >> 2;       // N quarter (16 cols)
    const int lr = lane >> 2, lc = lane & 3;
    const bool has3 = (wm < 3);    // u=2 frag valid (f = wm+8 < 11)

    float2 bv[2];
#pragma unroll
    for (int nf = 0; nf < 2; nf++)
        bv[nf] = ((const float2*)bias)[(wn * 16 + nf * 8 + 2 * lc) >> 1];

    // fragment row bases (clamped): rows n = (wm+4u)*16 + h*8 + lr
    int base[3][2], baseAdj[3][2];
#pragma unroll
    for (int u = 0; u < 3; u++) {
#pragma unroll
        for (int h = 0; h < 2; h++) {
            int n = (wm + 4 * u) * 16 + h * 8 + lr;
            if (n > 164) n = 164;
            int hr = n / 15, hc = n - 15 * hr;
            int bb = ((hr + 1) * 17 + (hc + 1)) * CELLB + 16 * lc;
            base[u][h]    = bb;
            baseAdj[u][h] = bb - (((hr + 1) & 1) ? CELLB : 0);
        }
    }

    // ---- staging map: 1320 uint4 groups; thread owns g = tid + 512j, j<3 ----
    int gdst[3];
#pragma unroll
    for (int j = 0; j < 3; j++) {
        int g = tid + THREADS * j;
        if (g < NHEX * 8) {
            int n = g >> 3, d8 = g & 7;
            int hr = n / 15, hc = n - 15 * hr;
            gdst[j] = ((hr + 1) * 17 + (hc + 1)) * CELLB + d8 * 16;
        } else gdst[j] = -1;
    }

    __syncthreads();   // zero + W staging complete

    // ---- convert first batch into buffer 0 ----
    {
        const float4* xs = (const float4*)(x + (size_t)blockIdx.x * (NHEX * HD));
#pragma unroll
        for (int j = 0; j < 3; j++)
            if (gdst[j] >= 0) {
                int g = tid + THREADS * j;
                float4 v0 = xs[2 * g], v1 = xs[2 * g + 1];
                *(uint4*)(G0 + gdst[j]) = make_uint4(pk(v0.x, v0.y), pk(v0.z, v0.w),
                                                     pk(v1.x, v1.y), pk(v1.z, v1.w));
            }
    }
    __syncthreads();   // buffer 0 ready

    int ib = 0;
    for (int b = blockIdx.x; b < NB; b += GRIDX) {
        char* cur = (ib == 0) ? G0 : G1;
        char* nxt = (ib == 0) ? G1 : G0;

        // ---- convert next batch into idle buffer (overlaps compute; no barrier) ----
        const int bn = b + GRIDX;
        if (bn < NB) {
            const float4* xs = (const float4*)(x + (size_t)bn * (NHEX * HD));
#pragma unroll
            for (int j = 0; j < 3; j++)
                if (gdst[j] >= 0) {
                    int g = tid + THREADS * j;
                    float4 v0 = xs[2 * g], v1 = xs[2 * g + 1];
                    *(uint4*)(nxt + gdst[j]) = make_uint4(pk(v0.x, v0.y), pk(v0.z, v0.w),
                                                          pk(v1.x, v1.y), pk(v1.z, v1.w));
                }
        }

        float acc[3][2][4];
#pragma unroll
        for (int u = 0; u < 3; u++)
#pragma unroll
            for (int nf = 0; nf < 2; nf++)
#pragma unroll
                for (int i = 0; i < 4; i++) acc[u][nf][i] = 0.f;

        const char* Wp0 = Wc + (wn * 16 + lr) * WROWB + 16 * lc;

#pragma unroll 1
        for (int c = 0; c < NCHUNK; c++) {
            const int off  = OFFC[c];
            const bool adj = (c < 2 || c > 4);
            const char* wp = Wp0 + c * 128;

            // ---- W frags (4 loads) ----
            uint4 w00 = *(const uint4*)(wp);
            uint4 w01 = *(const uint4*)(wp + 64);
            uint4 w10 = *(const uint4*)(wp + 8 * WROWB);
            uint4 w11 = *(const uint4*)(wp + 8 * WROWB + 64);

            // ---- A frags for u=0 and u=1 (8 loads; 12 in flight with W) ----
            const int p00 = (adj ? baseAdj[0][0] : base[0][0]) + off;
            const int p01 = (adj ? baseAdj[0][1] : base[0][1]) + off;
            const int p10 = (adj ? baseAdj[1][0] : base[1][0]) + off;
            const int p11 = (adj ? baseAdj[1][1] : base[1][1]) + off;
            uint4 a0h0s0 = *(const uint4*)(cur + p00);
            uint4 a0h0s1 = *(const uint4*)(cur + p00 + 64);
            uint4 a0h1s0 = *(const uint4*)(cur + p01);
            uint4 a0h1s1 = *(const uint4*)(cur + p01 + 64);
            uint4 a1h0s0 = *(const uint4*)(cur + p10);
            uint4 a1h0s1 = *(const uint4*)(cur + p10 + 64);
            uint4 a1h1s0 = *(const uint4*)(cur + p11);
            uint4 a1h1s1 = *(const uint4*)(cur + p11 + 64);

            // ---- MMAs u=0 ----
            mma16816(acc[0][0], a0h0s0.x, a0h1s0.x, a0h0s0.y, a0h1s0.y, w00.x, w00.y);
            mma16816(acc[0][1], a0h0s0.x, a0h1s0.x, a0h0s0.y, a0h1s0.y, w10.x, w10.y);
            mma16816(acc[0][0], a0h0s0.z, a0h1s0.z, a0h0s0.w, a0h1s0.w, w00.z, w00.w);
            mma16816(acc[0][1], a0h0s0.z, a0h1s0.z, a0h0s0.w, a0h1s0.w, w10.z, w10.w);
            mma16816(acc[0][0], a0h0s1.x, a0h1s1.x, a0h0s1.y, a0h1s1.y, w01.x, w01.y);
            mma16816(acc[0][1], a0h0s1.x, a0h1s1.x, a0h0s1.y, a0h1s1.y, w11.x, w11.y);
            mma16816(acc[0][0], a0h0s1.z, a0h1s1.z, a0h0s1.w, a0h1s1.w, w01.z, w01.w);
            mma16816(acc[0][1], a0h0s1.z, a0h1s1.z, a0h0s1.w, a0h1s1.w, w11.z, w11.w);
            // ---- MMAs u=1 ----
            mma16816(acc[1][0], a1h0s0.x, a1h1s0.x, a1h0s0.y, a1h1s0.y, w00.x, w00.y);
            mma16816(acc[1][1], a1h0s0.x, a1h1s0.x, a1h0s0.y, a1h1s0.y, w10.x, w10.y);
            mma16816(acc[1][0], a1h0s0.z, a1h1s0.z, a1h0s0.w, a1h1s0.w, w00.z, w00.w);
            mma16816(acc[1][1], a1h0s0.z, a1h1s0.z, a1h0s0.w, a1h1s0.w, w10.z, w10.w);
            mma16816(acc[1][0], a1h0s1.x, a1h1s1.x, a1h0s1.y, a1h1s1.y, w01.x, w01.y);
            mma16816(acc[1][1], a1h0s1.x, a1h1s1.x, a1h0s1.y, a1h1s1.y, w11.x, w11.y);
            mma16816(acc[1][0], a1h0s1.z, a1h1s1.z, a1h0s1.w, a1h1s1.w, w01.z, w01.w);
            mma16816(acc[1][1], a1h0s1.z, a1h1s1.z, a1h0s1.w, a1h1s1.w, w11.z, w11.w);

            // ---- u=2 (guarded): 4 loads + 8 MMAs ----
            if (has3) {
                const int p20 = (adj ? baseAdj[2][0] : base[2][0]) + off;
                const int p21 = (adj ? baseAdj[2][1] : base[2][1]) + off;
                uint4 b0s0 = *(const uint4*)(cur + p20);
                uint4 b0s1 = *(const uint4*)(cur + p20 + 64);
                uint4 b1s0 = *(const uint4*)(cur + p21);
                uint4 b1s1 = *(const uint4*)(cur + p21 + 64);
                mma16816(acc[2][0], b0s0.x, b1s0.x, b0s0.y, b1s0.y, w00.x, w00.y);
                mma16816(acc[2][1], b0s0.x, b1s0.x, b0s0.y, b1s0.y, w10.x, w10.y);
                mma16816(acc[2][0], b0s0.z, b1s0.z, b0s0.w, b1s0.w, w00.z, w00.w);
                mma16816(acc[2][1], b0s0.z, b1s0.z, b0s0.w, b1s0.w, w10.z, w10.w);
                mma16816(acc[2][0], b0s1.x, b1s1.x, b0s1.y, b1s1.y, w01.x, w01.y);
                mma16816(acc[2][1], b0s1.x, b1s1.x, b0s1.y, b1s1.y, w11.x, w11.y);
                mma16816(acc[2][0], b0s1.z, b1s1.z, b0s1.w, b1s1.w, w01.z, w01.w);
                mma16816(acc[2][1], b0s1.z, b1s1.z, b0s1.w, b1s1.w, w11.z, w11.w);
            }
        }

        // ---- epilogue: bias + masked stores ----
        float* ob = out + (size_t)b * (NHEX * OUTD);
#pragma unroll
        for (int u = 0; u < 3; u++) {
            if (u < 2 || has3) {
                const int f = wm + 4 * u;
                const int n1 = f * 16 + lr, n2 = n1 + 8;
#pragma unroll
                for (int nf = 0; nf < 2; nf++) {
                    const int cc = wn * 16 + nf * 8 + 2 * lc;
                    if (n1 < NHEX) {
                        float2 v = make_float2(acc[u][nf][0] + bv[nf].x,
                                               acc[u][nf][1] + bv[nf].y);
                        *(float2*)(ob + n1 * OUTD + cc) = v;
                    }
                    if (n2 < NHEX) {
                        float2 v = make_float2(acc[u][nf][2] + bv[nf].x,
                                               acc[u][nf][3] + bv[nf].y);
                        *(float2*)(ob + n2 * OUTD + cc) = v;
                    }
                }
            }
        }

        __syncthreads();   // publish next buffer; retire current
        ib ^= 1;
    }
}

extern "C" void kernel_launch(void* const* d_in, const int* in_sizes, int n_in,
                              void* d_out, int out_size)
{
    const float* x    = (const float*)d_in[0];
    const float* W    = (const float*)d_in[1];
    const float* bias = (const float*)d_in[2];
    float* out = (float*)d_out;

    cudaFuncSetAttribute(hexconv_mma,
                         cudaFuncAttributeMaxDynamicSharedMemorySize,
                         (int)SMEM_BYTES);
    hexconv_mma<<<GRIDX, THREADS, SMEM_BYTES>>>(x, W, bias, out);
}

// round 16
// speedup vs baseline: 1.1099x; 1.1099x over previous
#include <cuda_runtime.h>
#include <cuda_fp16.h>
#include <cstdint>

// HexConv, persistent-CTA fp16 mma.sync (m16n8k16, f32 accum):
//   R10's exact warp layout + mainloop (16 warps = 4 M-groups x 4 N-quarters,
//   frags f = wm+4u, u<3, 24 acc; 4-wide MLP load bursts) + double-buffered fp16
//   grid with REGISTER-PREFETCH convert pipeline (the R10 ingredient whose removal
//   cost R11/R14/R15 ~10us):
//     per batch: STS pf(b+1)->nxt (no stall, nxt idle -> no pre-barrier),
//                LDG(b+2)->pf (hidden), compute(b) from cur, ONE barrier.
// K-permutation: per 32-k superblock, thread lc owns orig d = 8lc..8lc+7 -> all
// operand traffic LDS.128; CELLB/WROWB == 64 mod 128 -> conflict-free phases.

#define NHEX   165
#define HD     64
#define OUTD   64
#define NCHUNK 7
#define CELLB  192
#define WROWB  960
#define NB     2048
#define THREADS 512
#define GRIDX  152

#define G_BYTES (221 * CELLB)                 // 42432 per buffer
#define W_BYTES (OUTD * WROWB)                // 61440
#define SMEM_BYTES (2 * G_BYTES + W_BYTES)    // 146304

__constant__ int OFFC[7] = {-17 * CELLB, -16 * CELLB, -1 * CELLB, 0,
                            1 * CELLB, 17 * CELLB, 18 * CELLB};

static __device__ __forceinline__ uint32_t pk(float a, float b) {
    __half2 h = __floats2half2_rn(a, b);
    return *(uint32_t*)&h;
}
static __device__ __forceinline__ void mma16816(float* c,
                                                uint32_t a0, uint32_t a1, uint32_t a2, uint32_t a3,
                                                uint32_t b0, uint32_t b1) {
    asm volatile(
        "mma.sync.aligned.m16n8k16.row.col.f32.f16.f16.f32 "
        "{%0,%1,%2,%3}, {%4,%5,%6,%7}, {%8,%9}, {%0,%1,%2,%3};"
        : "+f"(c[0]), "+f"(c[1]), "+f"(c[2]), "+f"(c[3])
        : "r"(a0), "r"(a1), "r"(a2), "r"(a3), "r"(b0), "r"(b1));
}

__global__ void __launch_bounds__(THREADS, 1)
hexconv_mma(const float* __restrict__ x, const float* __restrict__ W,
            const float* __restrict__ bias, float* __restrict__ out)
{
    extern __shared__ char smem[];
    char* G0 = smem;
    char* G1 = smem + G_BYTES;
    char* Wc = smem + 2 * G_BYTES;
    const int tid = threadIdx.x;

    // ---- one-time: zero both grid buffers (pad cells stay zero forever) ----
    for (int i = tid; i < 2 * G_BYTES / 16; i += THREADS)
        ((uint4*)smem)[i] = make_uint4(0, 0, 0, 0);

    // ---- one-time: stage W as fp16 ----
    const float4* Wg4 = (const float4*)W;
    for (int i = tid; i < OUTD * 112; i += THREADS) {
        int o = i / 112, k4 = i - o * 112;
        float4 v = Wg4[i];
        *(uint2*)(Wc + o * WROWB + k4 * 8) = make_uint2(pk(v.x, v.y), pk(v.z, v.w));
    }

    // ---- warp geometry: 16 warps = 4 M-groups x 4 N-quarters (R10 layout) ----
    const int wid = tid >> 5, lane = tid & 31;
    const int wm = wid & 3;        // M group: frags f = wm + 4u, u < 3
    const int wn = wid >> 2;       // N quarter (16 cols)
    const int lr = lane >> 2, lc = lane & 3;
    const bool has3 = (wm < 3);    // u=2 frag valid (f = wm+8 < 11)

    float2 bv[2];
#pragma unroll
    for (int nf = 0; nf < 2; nf++)
        bv[nf] = ((const float2*)bias)[(wn * 16 + nf * 8 + 2 * lc) >> 1];

    // fragment row bases (clamped): rows n = (wm+4u)*16 + h*8 + lr
    int base2[3][2], parC[3][2];
#pragma unroll
    for (int u = 0; u < 3; u++) {
#pragma unroll
        for (int h = 0; h < 2; h++) {
            int n = (wm + 4 * u) * 16 + h * 8 + lr;
            if (n > 164) n = 164;
            int hr = n / 15, hc = n - 15 * hr;
            base2[u][h] = ((hr + 1) * 17 + (hc + 1)) * CELLB + 16 * lc;
            parC[u][h]  = ((hr + 1) & 1) ? CELLB : 0;
        }
    }

    // ---- staging map: 1320 uint4 groups; thread owns g = tid + 512j, j<3 ----
    float4 pf[3][2];
    int gdst[3];
#pragma unroll
    for (int j = 0; j < 3; j++) {
        int g = tid + THREADS * j;
        if (g < NHEX * 8) {
            int n = g >> 3, d8 = g & 7;
            int hr = n / 15, hc = n - 15 * hr;
            gdst[j] = ((hr + 1) * 17 + (hc + 1)) * CELLB + d8 * 16;
        } else gdst[j] = -1;
    }

    // ---- prologue: LDG b0 -> pf; cvt+STS -> G0; LDG b1 -> pf ----
    {
        const float4* xs = (const float4*)(x + (size_t)blockIdx.x * (NHEX * HD));
#pragma unroll
        for (int j = 0; j < 3; j++)
            if (gdst[j] >= 0) {
                int g = tid + THREADS * j;
                pf[j][0] = xs[2 * g];
                pf[j][1] = xs[2 * g + 1];
            }
    }
    __syncthreads();   // zeroing + W staging complete before STS
#pragma unroll
    for (int j = 0; j < 3; j++)
        if (gdst[j] >= 0)
            *(uint4*)(G0 + gdst[j]) = make_uint4(pk(pf[j][0].x, pf[j][0].y),
                                                 pk(pf[j][0].z, pf[j][0].w),
                                                 pk(pf[j][1].x, pf[j][1].y),
                                                 pk(pf[j][1].z, pf[j][1].w));
    if (blockIdx.x + GRIDX < NB) {
        const float4* xs = (const float4*)(x + (size_t)(blockIdx.x + GRIDX) * (NHEX * HD));
#pragma unroll
        for (int j = 0; j < 3; j++)
            if (gdst[j] >= 0) {
                int g = tid + THREADS * j;
                pf[j][0] = xs[2 * g];
                pf[j][1] = xs[2 * g + 1];
            }
    }
    __syncthreads();   // G0 ready

    int ib = 0;
    for (int b = blockIdx.x; b < NB; b += GRIDX) {
        char* cur = (ib == 0) ? G0 : G1;
        char* nxt = (ib == 0) ? G1 : G0;

        // ---- STS pf (batch b+1, already in regs) -> idle buffer: zero-stall ----
        if (b + GRIDX < NB) {
#pragma unroll
            for (int j = 0; j < 3; j++)
                if (gdst[j] >= 0)
                    *(uint4*)(nxt + gdst[j]) = make_uint4(pk(pf[j][0].x, pf[j][0].y),
                                                          pk(pf[j][0].z, pf[j][0].w),
                                                          pk(pf[j][1].x, pf[j][1].y),
                                                          pk(pf[j][1].z, pf[j][1].w));
        }
        // ---- LDG batch b+2 -> pf: consumed next iteration (fully hidden) ----
        if (b + 2 * GRIDX < NB) {
            const float4* xs = (const float4*)(x + (size_t)(b + 2 * GRIDX) * (NHEX * HD));
#pragma unroll
            for (int j = 0; j < 3; j++)
                if (gdst[j] >= 0) {
                    int g = tid + THREADS * j;
                    pf[j][0] = xs[2 * g];
                    pf[j][1] = xs[2 * g + 1];
                }
        }

        float acc[3][2][4];
#pragma unroll
        for (int u = 0; u < 3; u++)
#pragma unroll
            for (int nf = 0; nf < 2; nf++)
#pragma unroll
                for (int i = 0; i < 4; i++) acc[u][nf][i] = 0.f;

        const char* Wp0 = Wc + (wn * 16 + lr) * WROWB + 16 * lc;

#pragma unroll 1
        for (int c = 0; c < NCHUNK; c++) {
            const int off  = OFFC[c];
            const bool adj = (c < 2 || c > 4);

            const char* wp = Wp0 + c * 128;
            uint4 w00 = *(const uint4*)(wp);
            uint4 w01 = *(const uint4*)(wp + 64);
            uint4 w10 = *(const uint4*)(wp + 8 * WROWB);
            uint4 w11 = *(const uint4*)(wp + 8 * WROWB + 64);

#pragma unroll
            for (int u = 0; u < 3; u++) {
                if (u < 2 || has3) {
                    const int p0 = base2[u][0] + off - (adj ? parC[u][0] : 0);
                    const int p1 = base2[u][1] + off - (adj ? parC[u][1] : 0);
                    uint4 a00 = *(const uint4*)(cur + p0);
                    uint4 a01 = *(const uint4*)(cur + p0 + 64);
                    uint4 a10 = *(const uint4*)(cur + p1);
                    uint4 a11 = *(const uint4*)(cur + p1 + 64);
                    mma16816(acc[u][0], a00.x, a10.x, a00.y, a10.y, w00.x, w00.y);
                    mma16816(acc[u][1], a00.x, a10.x, a00.y, a10.y, w10.x, w10.y);
                    mma16816(acc[u][0], a00.z, a10.z, a00.w, a10.w, w00.z, w00.w);
                    mma16816(acc[u][1], a00.z, a10.z, a00.w, a10.w, w10.z, w10.w);
                    mma16816(acc[u][0], a01.x, a11.x, a01.y, a11.y, w01.x, w01.y);
                    mma16816(acc[u][1], a01.x, a11.x, a01.y, a11.y, w11.x, w11.y);
                    mma16816(acc[u][0], a01.z, a11.z, a01.w, a11.w, w01.z, w01.w);
                    mma16816(acc[u][1], a01.z, a11.z, a01.w, a11.w, w11.z, w11.w);
                }
            }
        }

        // ---- epilogue: bias + masked stores ----
        float* ob = out + (size_t)b * (NHEX * OUTD);
#pragma unroll
        for (int u = 0; u < 3; u++) {
            if (u < 2 || has3) {
                const int f = wm + 4 * u;
                const int n1 = f * 16 + lr, n2 = n1 + 8;
#pragma unroll
                for (int nf = 0; nf < 2; nf++) {
                    const int cc = wn * 16 + nf * 8 + 2 * lc;
                    if (n1 < NHEX) {
                        float2 v = make_float2(acc[u][nf][0] + bv[nf].x,
                                               acc[u][nf][1] + bv[nf].y);
                        *(float2*)(ob + n1 * OUTD + cc) = v;
                    }
                    if (n2 < NHEX) {
                        float2 v = make_float2(acc[u][nf][2] + bv[nf].x,
                                               acc[u][nf][3] + bv[nf].y);
                        *(float2*)(ob + n2 * OUTD + cc) = v;
                    }
                }
            }
        }

        __syncthreads();   // publish nxt; retire cur (single barrier per batch)
        ib ^= 1;
    }
}

extern "C" void kernel_launch(void* const* d_in, const int* in_sizes, int n_in,
                              void* d_out, int out_size)
{
    const float* x    = (const float*)d_in[0];
    const float* W    = (const float*)d_in[1];
    const float* bias = (const float*)d_in[2];
    float* out = (float*)d_out;

    cudaFuncSetAttribute(hexconv_mma,
                         cudaFuncAttributeMaxDynamicSharedMemorySize,
                         (int)SMEM_BYTES);
    hexconv_mma<<<GRIDX, THREADS, SMEM_BYTES>>>(x, W, bias, out);
}